// round 1
// baseline (speedup 1.0000x reference)
#include <cuda_runtime.h>
#include <cstdint>

// ---------------------------------------------------------------------------
// Sequential LSTM rollout, 10000 steps, H=1024.
// 128 persistent CTAs (<=148 SMs -> guaranteed co-resident), W_hh in registers
// (f32x2 pairs), h broadcast via double-buffered __device__ array with
// release/acquire flags (no cooperative launch needed).
// CTA b owns h indices [8b, 8b+8) and gate rows {g*1024 + 8b + j}.
// Warp w owns k in [128w, 128w+128). Lane l owns local gate row l.
// ---------------------------------------------------------------------------

#define HDIM  1024
#define NCTA  128
#define TPB   256
#define NWARP 8
#define KPW   128          // k elements per warp
#define WPT   (KPW/2)      // f32x2 weight pairs per thread = 64

typedef unsigned long long ull;

__device__ __align__(16) float    g_hbuf[2][HDIM];
__device__ unsigned               g_flag[2][NCTA];

__device__ __forceinline__ ull ffma2(ull a, ull b, ull c) {
    ull d;
    asm("fma.rn.f32x2 %0, %1, %2, %3;" : "=l"(d) : "l"(a), "l"(b), "l"(c));
    return d;
}
__device__ __forceinline__ ull fadd2(ull a, ull b) {
    ull d;
    asm("add.rn.f32x2 %0, %1, %2;" : "=l"(d) : "l"(a), "l"(b));
    return d;
}
__device__ __forceinline__ float pairsum(ull a) {
    float lo = __uint_as_float((unsigned)(a & 0xffffffffull));
    float hi = __uint_as_float((unsigned)(a >> 32));
    return lo + hi;
}
__device__ __forceinline__ float sigf(float x) {
    return 1.0f / (1.0f + __expf(-x));
}

__global__ void __launch_bounds__(TPB) lstm_init_kernel() {
    int t = threadIdx.x;
    if (t < NCTA) { g_flag[0][t] = 0u; g_flag[1][t] = 0u; }
}

__global__ void __launch_bounds__(TPB) lstm_kernel(
    const float* __restrict__ x,      // [1024]
    const float* __restrict__ W_ih,   // [4096,1024] row-major
    const float* __restrict__ W_hh,   // [4096,1024] row-major
    const float* __restrict__ b_ih,   // [4096]
    const float* __restrict__ b_hh,   // [4096]
    float* __restrict__ out,          // [N,1024]
    int N)
{
    __shared__ float sh_h[HDIM];
    __shared__ float sh_part[NWARP * 32];

    const int tid = threadIdx.x;
    const int w   = tid >> 5;
    const int l   = tid & 31;
    const int cta = blockIdx.x;
    const int gt  = l >> 3;          // gate 0..3 (i,f,g,o)
    const int jj  = l & 7;           // local h index 0..7
    const int rowG = gt * HDIM + cta * 8 + jj;   // global gate row for lane l

    // ---- stage x into shared (reuse sh_h as x buffer) ----
    ((float4*)sh_h)[tid] = ((const float4*)x)[tid];   // 256 * 4 = 1024 floats
    __syncthreads();

    // ---- prologue: x_gates = x @ W_ih^T + b_ih + b_hh, rows of this CTA ----
    float xgi = 0.f, xgf = 0.f, xgg = 0.f, xgo = 0.f;
    {
        const ull* wp = (const ull*)W_ih + (size_t)rowG * (HDIM / 2) + w * WPT;
        const ull* hp = (const ull*)sh_h + w * WPT;
        ull a0 = 0, a1 = 0, a2 = 0, a3 = 0;
        #pragma unroll
        for (int i = 0; i < WPT; i += 4) {
            a0 = ffma2(wp[i + 0], hp[i + 0], a0);
            a1 = ffma2(wp[i + 1], hp[i + 1], a1);
            a2 = ffma2(wp[i + 2], hp[i + 2], a2);
            a3 = ffma2(wp[i + 3], hp[i + 3], a3);
        }
        a0 = fadd2(a0, a1); a2 = fadd2(a2, a3); a0 = fadd2(a0, a2);
        sh_part[w * 32 + l] = pairsum(a0);
        __syncthreads();
        if (w == 0) {
            float s = 0.f;
            #pragma unroll
            for (int ww = 0; ww < NWARP; ww++) s += sh_part[ww * 32 + l];
            s += b_ih[rowG] + b_hh[rowG];
            float s_f = __shfl_sync(0xffffffffu, s, l + 8);
            float s_g = __shfl_sync(0xffffffffu, s, l + 16);
            float s_o = __shfl_sync(0xffffffffu, s, l + 24);
            if (l < 8) { xgi = s; xgf = s_f; xgg = s_g; xgo = s_o; }
        }
        __syncthreads();
    }

    // ---- preload W_hh slice into registers (64 f32x2 pairs / thread) ----
    ull wreg[WPT];
    {
        const ull* wp = (const ull*)W_hh + (size_t)rowG * (HDIM / 2) + w * WPT;
        #pragma unroll
        for (int i = 0; i < WPT; i++) wreg[i] = wp[i];
    }

    // ---- recurrence ----
    float c = 0.f;
    for (int t = 0; t < N; ++t) {
        float dot = 0.f;
        if (t > 0) {
            const int p = (t - 1) & 1;
            // wait for all chunks of h_{t-1}
            if (tid < NCTA) {
                const unsigned* fp = &g_flag[p][tid];
                unsigned v;
                do {
                    asm volatile("ld.acquire.gpu.u32 %0, [%1];"
                                 : "=r"(v) : "l"(fp));
                } while ((int)v < t);
            }
            __syncthreads();
            // stage h_{t-1} into shared (L2-direct: peer-SM writes)
            ((float4*)sh_h)[tid] = __ldcg((const float4*)g_hbuf[p] + tid);
            __syncthreads();

            const ull* hp = (const ull*)sh_h + w * WPT;
            ull a0 = 0, a1 = 0, a2 = 0, a3 = 0;
            #pragma unroll
            for (int i = 0; i < WPT; i += 4) {
                a0 = ffma2(wreg[i + 0], hp[i + 0], a0);
                a1 = ffma2(wreg[i + 1], hp[i + 1], a1);
                a2 = ffma2(wreg[i + 2], hp[i + 2], a2);
                a3 = ffma2(wreg[i + 3], hp[i + 3], a3);
            }
            a0 = fadd2(a0, a1); a2 = fadd2(a2, a3); a0 = fadd2(a0, a2);
            dot = pairsum(a0);
        }
        sh_part[w * 32 + l] = dot;
        __syncthreads();

        if (w == 0) {
            float s = 0.f;
            #pragma unroll
            for (int ww = 0; ww < NWARP; ww++) s += sh_part[ww * 32 + l];
            float s_f = __shfl_sync(0xffffffffu, s, l + 8);
            float s_g = __shfl_sync(0xffffffffu, s, l + 16);
            float s_o = __shfl_sync(0xffffffffu, s, l + 24);
            if (l < 8) {
                float iv = sigf(xgi + s);
                float fv = sigf(xgf + s_f);
                float gv = tanhf(xgg + s_g);
                float ov = sigf(xgo + s_o);
                c = fv * c + iv * gv;
                float hn = ov * tanhf(c);
                g_hbuf[t & 1][cta * 8 + l] = hn;
                __stcs(out + (size_t)t * HDIM + cta * 8 + l, hn);
            }
        }
        __syncthreads();
        if (tid == 0) {
            __threadfence();
            asm volatile("st.release.gpu.u32 [%0], %1;"
                         :: "l"(&g_flag[t & 1][cta]), "r"((unsigned)(t + 1))
                         : "memory");
        }
    }
}

extern "C" void kernel_launch(void* const* d_in, const int* in_sizes, int n_in,
                              void* d_out, int out_size) {
    const float* x    = (const float*)d_in[0];
    const float* W_ih = (const float*)d_in[1];
    const float* W_hh = (const float*)d_in[2];
    const float* b_ih = (const float*)d_in[3];
    const float* b_hh = (const float*)d_in[4];
    float* out = (float*)d_out;
    const int N = out_size / HDIM;   // num_nodes (avoids reading device scalar)

    lstm_init_kernel<<<1, TPB>>>();
    lstm_kernel<<<NCTA, TPB>>>(x, W_ih, W_hh, b_ih, b_hh, out, N);
}